// round 3
// baseline (speedup 1.0000x reference)
#include <cuda_runtime.h>
#include <math.h>

#define BLK 256
#define NAG 32
#define NA  4096      // B*N agents
#define DD  256
#define NE  31        // N-1 edges per agent

// d_out offsets (concatenated outputs, fp32)
#define OFF_LOG 2097152L
#define OFF_UNN 2224128L
#define OFF_ENT 2351104L
#define OFF_HW  2351105L
#define OFF_CMB 2478081L

// ------- scratch (static __device__; no allocations allowed) -------
__device__ float g_H1[NA * 128];
__device__ float g_AE[NA * DD];
__device__ float g_BASE[NA * DD];
__device__ float g_FIN[NA * 512];
__device__ float g_ENT[NA];
__device__ float g_W2e[2 * DD];   // he_w @ hm2_w folded
__device__ float g_b2e[2];        // he_w @ hm2_b + he_b
__device__ float g_QKW[DD * 10];  // q_w^T @ k_w folded
__device__ float g_pW2e[8 * 512];
__device__ float g_pQKW[8 * DD * 10];
__device__ float g_pb2e[16];

// ------- f32x2 packed helpers (Blackwell FFMA2 path) -------
__device__ __forceinline__ unsigned long long dup2(float x) {
    unsigned long long r;
    unsigned u = __float_as_uint(x);
    asm("mov.b64 %0, {%1, %2};" : "=l"(r) : "r"(u), "r"(u));
    return r;
}
__device__ __forceinline__ void ffma2(unsigned long long& d,
                                      unsigned long long a, unsigned long long b) {
    asm("fma.rn.f32x2 %0, %1, %2, %0;" : "+l"(d) : "l"(a), "l"(b));
}
__device__ __forceinline__ float2 unpack2(unsigned long long v) {
    unsigned lo, hi;
    asm("mov.b64 {%0, %1}, %2;" : "=r"(lo), "=r"(hi) : "l"(v));
    float2 r; r.x = __uint_as_float(lo); r.y = __uint_as_float(hi);
    return r;
}

// ------- fold stage A: 8 blocks, each handles a 32-wide K-slice -------
__global__ void foldA_kernel(const float* __restrict__ he_w,
                             const float* __restrict__ hm2_w, const float* __restrict__ hm2_b,
                             const float* __restrict__ q_w, const float* __restrict__ k_w)
{
    int p = blockIdx.x;
    int t = threadIdx.x;
    float s0 = 0.f, s1 = 0.f;
#pragma unroll 8
    for (int m = 0; m < 32; m++) {
        int mm = p * 32 + m;
        float w2 = hm2_w[mm * DD + t];
        s0 += he_w[mm] * w2;
        s1 += he_w[DD + mm] * w2;
    }
    g_pW2e[p * 512 + t] = s0;
    g_pW2e[p * 512 + 256 + t] = s1;

    float acc[10];
#pragma unroll
    for (int f = 0; f < 10; f++) acc[f] = 0.f;
#pragma unroll 4
    for (int d = 0; d < 32; d++) {
        int dd = p * 32 + d;
        float qv = q_w[dd * DD + t];
#pragma unroll
        for (int f = 0; f < 10; f++) acc[f] += qv * k_w[dd * 10 + f];
    }
#pragma unroll
    for (int f = 0; f < 10; f++) g_pQKW[(p * DD + t) * 10 + f] = acc[f];

    if (t < 2) {
        float s = 0.f;
        for (int m = 0; m < 32; m++) {
            int mm = p * 32 + m;
            s += he_w[t * DD + mm] * hm2_b[mm];
        }
        g_pb2e[p * 2 + t] = s;
    }
}

__global__ void foldB_kernel(const float* __restrict__ he_b)
{
    int t = threadIdx.x;
    float s0 = 0.f, s1 = 0.f;
#pragma unroll
    for (int p = 0; p < 8; p++) {
        s0 += g_pW2e[p * 512 + t];
        s1 += g_pW2e[p * 512 + 256 + t];
    }
    g_W2e[t] = s0;
    g_W2e[DD + t] = s1;
    float acc[10];
#pragma unroll
    for (int f = 0; f < 10; f++) acc[f] = 0.f;
#pragma unroll
    for (int p = 0; p < 8; p++)
#pragma unroll
        for (int f = 0; f < 10; f++) acc[f] += g_pQKW[(p * DD + t) * 10 + f];
#pragma unroll
    for (int f = 0; f < 10; f++) g_QKW[t * 10 + f] = acc[f];
    if (t < 2) {
        float s = he_b[t];
#pragma unroll
        for (int p = 0; p < 8; p++) s += g_pb2e[p * 2 + t];
        g_b2e[t] = s;
    }
}

// ------- H1 = leaky(emb[:,4:9] @ emb1_w^T + b) -------
__global__ void h1_kernel(const float* __restrict__ emb,
                          const float* __restrict__ w, const float* __restrict__ b,
                          float* __restrict__ H1)
{
    __shared__ float sw[128 * 5];
    __shared__ float sb[128];
    int tid = threadIdx.x;
    for (int e = tid; e < 640; e += 256) sw[e] = w[e];
    if (tid < 128) sb[tid] = b[tid];
    __syncthreads();
    int r = blockIdx.x * 2 + (tid >> 7);
    int c = tid & 127;
    const float* er = emb + (long)r * 11 + 4;
    float e0 = er[0], e1 = er[1], e2 = er[2], e3 = er[3], e4 = er[4];
    const float* wc = &sw[c * 5];
    float v = sb[c] + e0 * wc[0] + e1 * wc[1] + e2 * wc[2] + e3 * wc[3] + e4 * wc[4];
    v = v > 0.f ? v : 0.01f * v;
    H1[(long)r * 128 + c] = v;
}

// ------- FFMA2 tiled GEMM: C = act(A[MxK] @ W[NxK]^T + bias) -------
// BM=64, BN=64, BK=16, 128 threads, micro 4x8 (cols packed f32x2).
// As2 holds A duplicated (each value twice) so inner-loop A pairs are LDS.128.
// Requires M%64==0, N%64==0, K%16==0, lda%4==0.
template <int ACT>
__global__ void __launch_bounds__(128)
gemm_f2(const float* __restrict__ A, int lda,
        const float* __restrict__ W, int ldw,
        const float* __restrict__ bias,
        float* __restrict__ C, int ldc,
        float* __restrict__ C2, int ldc2, int K)
{
    const int BK = 16;
    __shared__ __align__(16) float As2[2][BK][128];  // duplicated pairs
    __shared__ __align__(16) float Ws[2][BK][64];
    int tid = threadIdx.x;
    int bm = blockIdx.y * 64, bn = blockIdx.x * 64;
    int tx = tid & 7, ty = tid >> 3;  // tx: 8 col-groups, ty: 16 row-groups

    unsigned long long acc[4][4];
#pragma unroll
    for (int i = 0; i < 4; i++)
#pragma unroll
        for (int j = 0; j < 4; j++) acc[i][j] = 0ull;

    int r = tid & 63, kh = (tid >> 6) * 8;
    const float* Arow = A + (long)(bm + r) * lda + kh;
    const float* Wrow = W + (long)(bn + r) * ldw + kh;
    bool w4 = ((ldw & 3) == 0);

    float4 ra0, ra1, rw0, rw1;
    float rws[8];

    // prologue load tile 0
    ra0 = *(const float4*)(Arow);
    ra1 = *(const float4*)(Arow + 4);
    if (w4) { rw0 = *(const float4*)(Wrow); rw1 = *(const float4*)(Wrow + 4); }
    else {
#pragma unroll
        for (int q = 0; q < 8; q++) rws[q] = Wrow[q];
    }
    {
        float av[8] = {ra0.x, ra0.y, ra0.z, ra0.w, ra1.x, ra1.y, ra1.z, ra1.w};
#pragma unroll
        for (int q = 0; q < 8; q++) {
            float2* p = (float2*)&As2[0][kh + q][2 * r];
            float2 d; d.x = av[q]; d.y = av[q];
            *p = d;
        }
        if (w4) {
            float wv[8] = {rw0.x, rw0.y, rw0.z, rw0.w, rw1.x, rw1.y, rw1.z, rw1.w};
#pragma unroll
            for (int q = 0; q < 8; q++) Ws[0][kh + q][r] = wv[q];
        } else {
#pragma unroll
            for (int q = 0; q < 8; q++) Ws[0][kh + q][r] = rws[q];
        }
    }
    __syncthreads();

    int nk = K / BK;
    int buf = 0;
    for (int t = 0; t < nk; t++) {
        if (t + 1 < nk) {
            const float* An = Arow + (t + 1) * BK;
            const float* Wn = Wrow + (t + 1) * BK;
            ra0 = *(const float4*)(An);
            ra1 = *(const float4*)(An + 4);
            if (w4) { rw0 = *(const float4*)(Wn); rw1 = *(const float4*)(Wn + 4); }
            else {
#pragma unroll
                for (int q = 0; q < 8; q++) rws[q] = Wn[q];
            }
        }
#pragma unroll
        for (int kk = 0; kk < BK; kk++) {
            // A: 4 duplicated pairs = 2x LDS.128
            ulonglong2 a01 = *(const ulonglong2*)&As2[buf][kk][ty * 8];
            ulonglong2 a23 = *(const ulonglong2*)&As2[buf][kk][ty * 8 + 4];
            // W: 4 native pairs = 2x LDS.128
            ulonglong2 w01 = *(const ulonglong2*)&Ws[buf][kk][tx * 8];
            ulonglong2 w23 = *(const ulonglong2*)&Ws[buf][kk][tx * 8 + 4];
            unsigned long long a[4] = {a01.x, a01.y, a23.x, a23.y};
            unsigned long long w[4] = {w01.x, w01.y, w23.x, w23.y};
#pragma unroll
            for (int i = 0; i < 4; i++)
#pragma unroll
                for (int j = 0; j < 4; j++) ffma2(acc[i][j], a[i], w[j]);
        }
        if (t + 1 < nk) {
            int nb = buf ^ 1;
            float av[8] = {ra0.x, ra0.y, ra0.z, ra0.w, ra1.x, ra1.y, ra1.z, ra1.w};
#pragma unroll
            for (int q = 0; q < 8; q++) {
                float2* p = (float2*)&As2[nb][kh + q][2 * r];
                float2 d; d.x = av[q]; d.y = av[q];
                *p = d;
            }
            if (w4) {
                float wv[8] = {rw0.x, rw0.y, rw0.z, rw0.w, rw1.x, rw1.y, rw1.z, rw1.w};
#pragma unroll
                for (int q = 0; q < 8; q++) Ws[nb][kh + q][r] = wv[q];
            } else {
#pragma unroll
                for (int q = 0; q < 8; q++) Ws[nb][kh + q][r] = rws[q];
            }
        }
        __syncthreads();
        buf ^= 1;
    }

    // epilogue
    float bs[8];
#pragma unroll
    for (int j = 0; j < 8; j++) bs[j] = bias ? bias[bn + tx * 8 + j] : 0.f;
#pragma unroll
    for (int i = 0; i < 4; i++) {
        long gm = bm + ty * 4 + i;
        float o[8];
#pragma unroll
        for (int j = 0; j < 4; j++) {
            float2 v = unpack2(acc[i][j]);
            o[2 * j] = v.x; o[2 * j + 1] = v.y;
        }
#pragma unroll
        for (int q = 0; q < 8; q++) {
            float v = o[q] + bs[q];
            if (ACT == 1) v = fmaxf(v, 0.f);
            if (ACT == 2) v = v > 0.f ? v : 0.01f * v;
            o[q] = v;
        }
        long gn = bn + tx * 8;
        *(float4*)&C[gm * ldc + gn] = *(float4*)&o[0];
        *(float4*)&C[gm * ldc + gn + 4] = *(float4*)&o[4];
        if (C2) {
            *(float4*)&C2[gm * ldc2 + gn] = *(float4*)&o[0];
            *(float4*)&C2[gm * ldc2 + gn + 4] = *(float4*)&o[4];
        }
    }
}

// ------- fused per-agent edge kernel -------
__global__ void edge_kernel(const float* __restrict__ emb,
                            const float* __restrict__ gum,
                            const float* __restrict__ hm1_w,
                            const float* __restrict__ v_w,
                            const float* __restrict__ v_b,
                            float* __restrict__ out)
{
    int a = blockIdx.x;
    int bb = a >> 5, i = a & 31;
    int tid = threadIdx.x;
    int lane = tid & 31, warp = tid >> 5;

    __shared__ float s_emb[NAG * 11];
    __shared__ float s_WE[DD * 7];   // hm1_w[:, 256:263]
    __shared__ float s_W2[2 * DD];
    __shared__ float s_b2[2];
    __shared__ float s_VW[DD * 10];
    __shared__ float s_vb[DD];
    __shared__ float s_base[DD];
    __shared__ float s_qk[10];
    __shared__ float s_se[NAG][10];
    __shared__ float s_sc[NAG];
    __shared__ float s_hw[NAG];
    __shared__ float s_cb[NAG];
    __shared__ float s_red[8 * 10];

    for (int e = tid; e < NAG * 11; e += BLK) s_emb[e] = emb[bb * NAG * 11 + e];
    for (int e = tid; e < DD * 7; e += BLK) s_WE[e] = hm1_w[(e / 7) * 263 + 256 + (e % 7)];
    s_W2[tid] = g_W2e[tid];
    s_W2[DD + tid] = g_W2e[DD + tid];
    for (int e = tid; e < DD * 10; e += BLK) s_VW[e] = v_w[e];
    s_vb[tid] = v_b[tid];
    s_base[tid] = g_BASE[(long)a * DD + tid];
    if (tid < 2) s_b2[tid] = g_b2e[tid];

    // qk[f] = sum_d AE[a,d] * QKW[d,f]
    float av = g_AE[(long)a * DD + tid];
#pragma unroll
    for (int f = 0; f < 10; f++) {
        float p = av * g_QKW[tid * 10 + f];
        for (int o = 16; o; o >>= 1) p += __shfl_down_sync(0xffffffffu, p, o);
        if (lane == 0) s_red[warp * 10 + f] = p;
    }
    __syncthreads();
    if (tid < 10) {
        float s = 0.f;
        for (int w = 0; w < 8; w++) s += s_red[w * 10 + tid];
        s_qk[tid] = s;
    }
    __syncthreads();

    // geometry + raw scores (threads 0..31 = edge j)
    if (tid < NAG) {
        int j = tid;
        if (j == i) {
            s_sc[j] = -1e30f; s_hw[j] = 0.f; s_cb[j] = 0.f;
#pragma unroll
            for (int f = 0; f < 10; f++) s_se[j][f] = 0.f;
        } else {
            const float* ei = &s_emb[i * 11];
            const float* ej = &s_emb[j * 11];
            float dx = ej[0] - ei[0], dy = ej[1] - ei[1];
            float r = sqrtf(dx * dx + dy * dy);
            float hx = ei[2], hy = ei[3];
            float hr = sqrtf(hx * hx + hy * hy);
            float inv = 1.f / (r * hr);
            float se[10];
            se[0] = r * (1.f / 12.f);
            se[1] = (dx * hx + dy * hy) * inv;
            se[2] = (dy * hx - dx * hy) * inv;
            se[3] = ej[2]; se[4] = ej[3];
            se[5] = ej[7]; se[6] = ej[8];
            float gx = ej[9] - ei[0], gy = ej[10] - ei[1];
            float gr = sqrtf(gx * gx + gy * gy);
            float ginv = 1.f / (gr * hr);
            se[7] = gr;
            se[8] = (gx * hx + gy * hy) * ginv;
            se[9] = (gy * hx - gx * hy) * ginv;
            float sc = 0.f;
#pragma unroll
            for (int f = 0; f < 10; f++) { s_se[j][f] = se[f]; sc += s_qk[f] * se[f]; }
            s_sc[j] = sc * 0.0625f;
            int jj = j - (j > i);
            out[OFF_UNN + (long)a * NE + jj] = r;
        }
    }
    __syncthreads();

    // hard logits: each warp owns 4 edges, register-blocked over edges
    {
        int jb = warp * 4;
        float e[4][7];
#pragma unroll
        for (int jj = 0; jj < 4; jj++)
#pragma unroll
            for (int f = 0; f < 7; f++) e[jj][f] = s_se[jb + jj][f];
        float acc0[4] = {0.f, 0.f, 0.f, 0.f}, acc1[4] = {0.f, 0.f, 0.f, 0.f};
#pragma unroll
        for (int t = 0; t < 8; t++) {
            int o = lane + t * 32;
            float base = s_base[o];
            const float* we = &s_WE[o * 7];
            float w0 = we[0], w1 = we[1], w2 = we[2], w3 = we[3],
                  w4 = we[4], w5 = we[5], w6 = we[6];
            float W2a = s_W2[o], W2b = s_W2[DD + o];
#pragma unroll
            for (int jj = 0; jj < 4; jj++) {
                float pre = base + w0 * e[jj][0] + w1 * e[jj][1] + w2 * e[jj][2]
                          + w3 * e[jj][3] + w4 * e[jj][4] + w5 * e[jj][5] + w6 * e[jj][6];
                float rr = fmaxf(pre, 0.f);
                acc0[jj] += W2a * rr;
                acc1[jj] += W2b * rr;
            }
        }
#pragma unroll
        for (int jj = 0; jj < 4; jj++) {
            for (int o = 16; o; o >>= 1) {
                acc0[jj] += __shfl_down_sync(0xffffffffu, acc0[jj], o);
                acc1[jj] += __shfl_down_sync(0xffffffffu, acc1[jj], o);
            }
        }
        if (lane == 0) {
#pragma unroll
            for (int jj = 0; jj < 4; jj++) {
                int j = jb + jj;
                if (j == i) continue;
                float l0 = acc0[jj] + s_b2[0], l1 = acc1[jj] + s_b2[1];
                int jx = j - (j > i);
                long gidx = ((long)a * NE + jx) * 2;
                float u0 = gum[gidx], u1 = gum[gidx + 1];
                float g0 = -logf(-logf(u0 + 1e-10f) + 1e-10f);
                float g1 = -logf(-logf(u1 + 1e-10f) + 1e-10f);
                float z0 = (l0 + g0) * 2.f, z1 = (l1 + g1) * 2.f;
                float zm = fmaxf(z0, z1);
                float x0 = expf(z0 - zm), x1 = expf(z1 - zm);
                float p1 = x1 / (x0 + x1);
                s_hw[j] = p1;
                out[OFF_LOG + (long)a * NE + jx] = l1;
                out[OFF_HW + (long)a * NE + jx] = p1;
            }
        }
    }
    __syncthreads();

    // score softmax, combined, entropy (warp 0)
    if (tid < NAG) {
        float sc = s_sc[tid];
        float m = sc;
        for (int o = 16; o; o >>= 1) m = fmaxf(m, __shfl_xor_sync(0xffffffffu, m, o));
        float ev = (tid == i) ? 0.f : expf(sc - m);
        float sum = ev;
        for (int o = 16; o; o >>= 1) sum += __shfl_xor_sync(0xffffffffu, sum, o);
        float sw = ev / sum;
        float cb = sw * s_hw[tid];
        s_cb[tid] = cb;
        float csum = cb;
        for (int o = 16; o; o >>= 1) csum += __shfl_xor_sync(0xffffffffu, csum, o);
        float cwn = cb / (csum + 1e-6f);
        float ent = (tid == i) ? 0.f : (-cwn * logf(cwn + 1e-6f));
        for (int o = 16; o; o >>= 1) ent += __shfl_xor_sync(0xffffffffu, ent, o);
        if (tid == 0) g_ENT[a] = ent;
        if (tid != i) out[OFF_CMB + (long)a * NE + (tid - (tid > i))] = cb;
    }
    __syncthreads();

    // x[a, o] = sum_j combined_j * relu(v_w[o]·se_j + v_b[o])
    {
        int o = tid;
        float vb = s_vb[o];
        float vw[10];
#pragma unroll
        for (int f = 0; f < 10; f++) vw[f] = s_VW[o * 10 + f];
        float acc = 0.f;
#pragma unroll 4
        for (int j = 0; j < NAG; j++) {
            float c = s_cb[j];   // 0 for j==i
            float vv = vb;
#pragma unroll
            for (int f = 0; f < 10; f++) vv += vw[f] * s_se[j][f];
            acc += c * fmaxf(vv, 0.f);
        }
        g_FIN[(long)a * 512 + 256 + o] = acc;
    }
}

// ------- deterministic entropy reduction -------
__global__ void ent_reduce(const float* __restrict__ ent, float* __restrict__ out)
{
    __shared__ float s[256];
    float v = 0.f;
    for (int k = threadIdx.x; k < NA; k += 256) v += ent[k];
    s[threadIdx.x] = v;
    __syncthreads();
    for (int o = 128; o; o >>= 1) {
        if (threadIdx.x < o) s[threadIdx.x] += s[threadIdx.x + o];
        __syncthreads();
    }
    if (threadIdx.x == 0) out[0] = s[0] * (1.f / 4096.f);
}

extern "C" void kernel_launch(void* const* d_in, const int* in_sizes, int n_in,
                              void* d_out, int out_size)
{
    const float* emb   = (const float*)d_in[0];
    const float* gum   = (const float*)d_in[1];
    const float* emb1w = (const float*)d_in[2];
    const float* emb1b = (const float*)d_in[3];
    const float* emb2w = (const float*)d_in[4];
    const float* emb2b = (const float*)d_in[5];
    const float* hm1w  = (const float*)d_in[6];
    const float* hm1b  = (const float*)d_in[7];
    const float* hm2w  = (const float*)d_in[8];
    const float* hm2b  = (const float*)d_in[9];
    const float* hew   = (const float*)d_in[10];
    const float* heb   = (const float*)d_in[11];
    const float* qw    = (const float*)d_in[12];
    const float* kw    = (const float*)d_in[13];
    const float* vw    = (const float*)d_in[14];
    const float* vb    = (const float*)d_in[15];
    const float* decw  = (const float*)d_in[16];
    const float* decb  = (const float*)d_in[17];
    float* out = (float*)d_out;

    float *pH1, *pAE, *pBASE, *pFIN, *pENT;
    cudaGetSymbolAddress((void**)&pH1, g_H1);
    cudaGetSymbolAddress((void**)&pAE, g_AE);
    cudaGetSymbolAddress((void**)&pBASE, g_BASE);
    cudaGetSymbolAddress((void**)&pFIN, g_FIN);
    cudaGetSymbolAddress((void**)&pENT, g_ENT);

    foldA_kernel<<<8, 256>>>(hew, hm2w, hm2b, qw, kw);
    foldB_kernel<<<1, 256>>>(heb);

    // H1 = leaky(emb[:,4:9] @ emb1_w^T + b)
    h1_kernel<<<NA / 2, 256>>>(emb, emb1w, emb1b, pH1);
    // AE = leaky(H1 @ emb2_w^T + b); mirror into FIN[:, 0:256]
    gemm_f2<2><<<dim3(256 / 64, NA / 64), 128>>>(pH1, 128, emb2w, 128, emb2b,
                                                 pAE, 256, pFIN, 512, 128);
    // BASE = AE @ hm1_w[:, :256]^T + hm1_b
    gemm_f2<0><<<dim3(256 / 64, NA / 64), 128>>>(pAE, 256, hm1w, 263, hm1b,
                                                 pBASE, 256, nullptr, 0, 256);
    // fused per-agent edge pipeline; writes FIN[:, 256:512] and 4 outputs
    edge_kernel<<<NA, 256>>>(emb, gum, hm1w, vw, vb, out);
    // output = FIN @ dec_w^T + dec_b
    gemm_f2<0><<<dim3(512 / 64, NA / 64), 128>>>(pFIN, 512, decw, 512, decb,
                                                 out, 512, nullptr, 0, 512);
    // mean entropy
    ent_reduce<<<1, 256>>>(pENT, out + OFF_ENT);
}

// round 4
// speedup vs baseline: 1.2177x; 1.2177x over previous
#include <cuda_runtime.h>
#include <math.h>

#define BLK 256
#define NAG 32
#define NA  4096      // B*N agents
#define DD  256
#define NE  31        // N-1 edges per agent

// d_out offsets (concatenated outputs, fp32)
#define OFF_LOG 2097152L
#define OFF_UNN 2224128L
#define OFF_ENT 2351104L
#define OFF_HW  2351105L
#define OFF_CMB 2478081L

// ------- scratch (static __device__; no allocations allowed) -------
__device__ float g_H1[NA * 128];
__device__ float g_AE[NA * DD];
__device__ float g_BASE[NA * DD];
__device__ float g_FIN[NA * 512];
__device__ float g_ENT[NA];
__device__ float g_W2e[2 * DD];   // he_w @ hm2_w folded
__device__ float g_b2e[2];        // he_w @ hm2_b + he_b
__device__ float g_QKW[DD * 10];  // q_w^T @ k_w folded
__device__ float g_pW2e[8 * 512];
__device__ float g_pQKW[8 * DD * 10];
__device__ float g_pb2e[16];

// ------- fold stage A: 8 blocks, each handles a 32-wide K-slice -------
__global__ void foldA_kernel(const float* __restrict__ he_w,
                             const float* __restrict__ hm2_w, const float* __restrict__ hm2_b,
                             const float* __restrict__ q_w, const float* __restrict__ k_w)
{
    int p = blockIdx.x;
    int t = threadIdx.x;
    float s0 = 0.f, s1 = 0.f;
#pragma unroll 8
    for (int m = 0; m < 32; m++) {
        int mm = p * 32 + m;
        float w2 = hm2_w[mm * DD + t];
        s0 += he_w[mm] * w2;
        s1 += he_w[DD + mm] * w2;
    }
    g_pW2e[p * 512 + t] = s0;
    g_pW2e[p * 512 + 256 + t] = s1;

    float acc[10];
#pragma unroll
    for (int f = 0; f < 10; f++) acc[f] = 0.f;
#pragma unroll 4
    for (int d = 0; d < 32; d++) {
        int dd = p * 32 + d;
        float qv = q_w[dd * DD + t];
#pragma unroll
        for (int f = 0; f < 10; f++) acc[f] += qv * k_w[dd * 10 + f];
    }
#pragma unroll
    for (int f = 0; f < 10; f++) g_pQKW[(p * DD + t) * 10 + f] = acc[f];

    if (t < 2) {
        float s = 0.f;
        for (int m = 0; m < 32; m++) {
            int mm = p * 32 + m;
            s += he_w[t * DD + mm] * hm2_b[mm];
        }
        g_pb2e[p * 2 + t] = s;
    }
}

__global__ void foldB_kernel(const float* __restrict__ he_b)
{
    int t = threadIdx.x;
    float s0 = 0.f, s1 = 0.f;
#pragma unroll
    for (int p = 0; p < 8; p++) {
        s0 += g_pW2e[p * 512 + t];
        s1 += g_pW2e[p * 512 + 256 + t];
    }
    g_W2e[t] = s0;
    g_W2e[DD + t] = s1;
    float acc[10];
#pragma unroll
    for (int f = 0; f < 10; f++) acc[f] = 0.f;
#pragma unroll
    for (int p = 0; p < 8; p++)
#pragma unroll
        for (int f = 0; f < 10; f++) acc[f] += g_pQKW[(p * DD + t) * 10 + f];
#pragma unroll
    for (int f = 0; f < 10; f++) g_QKW[t * 10 + f] = acc[f];
    if (t < 2) {
        float s = he_b[t];
#pragma unroll
        for (int p = 0; p < 8; p++) s += g_pb2e[p * 2 + t];
        g_b2e[t] = s;
    }
}

// ------- H1 = leaky(emb[:,4:9] @ emb1_w^T + b) -------
__global__ void h1_kernel(const float* __restrict__ emb,
                          const float* __restrict__ w, const float* __restrict__ b,
                          float* __restrict__ H1)
{
    __shared__ float sw[128 * 5];
    __shared__ float sb[128];
    int tid = threadIdx.x;
    for (int e = tid; e < 640; e += 256) sw[e] = w[e];
    if (tid < 128) sb[tid] = b[tid];
    __syncthreads();
    int r = blockIdx.x * 2 + (tid >> 7);
    int c = tid & 127;
    const float* er = emb + (long)r * 11 + 4;
    float e0 = er[0], e1 = er[1], e2 = er[2], e3 = er[3], e4 = er[4];
    const float* wc = &sw[c * 5];
    float v = sb[c] + e0 * wc[0] + e1 * wc[1] + e2 * wc[2] + e3 * wc[3] + e4 * wc[4];
    v = v > 0.f ? v : 0.01f * v;
    H1[(long)r * 128 + c] = v;
}

// ------- fp32 tiled GEMM: C = act(A[MxK] @ W[NxK]^T + bias) -------
// BM=64, BN=64, BK=16, 128 threads, micro 8x4. High-occupancy variant:
// 8KB smem, ~70 regs -> many resident blocks; grids of 256..512 blocks.
// Requires M%64==0, N%64==0, K%16==0, lda%4==0. ldw may be unaligned (scalar path).
template <int ACT>
__global__ void __launch_bounds__(128)
gemm_t2(const float* __restrict__ A, int lda,
        const float* __restrict__ W, int ldw,
        const float* __restrict__ bias,
        float* __restrict__ C, int ldc,
        float* __restrict__ C2, int ldc2, int K)
{
    const int BK = 16;
    __shared__ __align__(16) float As[BK][64];
    __shared__ __align__(16) float Ws[BK][64];
    int tid = threadIdx.x;
    int bm = blockIdx.y * 64, bn = blockIdx.x * 64;
    int tx = tid & 15, ty = tid >> 4;   // tx: 16 col-groups of 4, ty: 8 row-groups of 8

    float acc[8][4];
#pragma unroll
    for (int i = 0; i < 8; i++)
#pragma unroll
        for (int j = 0; j < 4; j++) acc[i][j] = 0.f;

    int r = tid & 63, kh = (tid >> 6) * 8;
    const float* Arow = A + (long)(bm + r) * lda + kh;
    const float* Wrow = W + (long)(bn + r) * ldw + kh;
    bool w4 = ((ldw & 3) == 0);

    for (int k0 = 0; k0 < K; k0 += BK) {
        // stage A: 64 rows x 16 cols (each thread: 8 cols of one row)
        {
            float4 a0 = *(const float4*)(Arow + k0);
            float4 a1 = *(const float4*)(Arow + k0 + 4);
            As[kh + 0][r] = a0.x; As[kh + 1][r] = a0.y;
            As[kh + 2][r] = a0.z; As[kh + 3][r] = a0.w;
            As[kh + 4][r] = a1.x; As[kh + 5][r] = a1.y;
            As[kh + 6][r] = a1.z; As[kh + 7][r] = a1.w;
        }
        if (w4) {
            float4 w0 = *(const float4*)(Wrow + k0);
            float4 w1 = *(const float4*)(Wrow + k0 + 4);
            Ws[kh + 0][r] = w0.x; Ws[kh + 1][r] = w0.y;
            Ws[kh + 2][r] = w0.z; Ws[kh + 3][r] = w0.w;
            Ws[kh + 4][r] = w1.x; Ws[kh + 5][r] = w1.y;
            Ws[kh + 6][r] = w1.z; Ws[kh + 7][r] = w1.w;
        } else {
#pragma unroll
            for (int q = 0; q < 8; q++) Ws[kh + q][r] = Wrow[k0 + q];
        }
        __syncthreads();
#pragma unroll
        for (int kk = 0; kk < BK; kk++) {
            float4 a0 = *(const float4*)&As[kk][ty * 8];
            float4 a1 = *(const float4*)&As[kk][ty * 8 + 4];
            float4 w0 = *(const float4*)&Ws[kk][tx * 4];
            float a[8] = {a0.x, a0.y, a0.z, a0.w, a1.x, a1.y, a1.z, a1.w};
            float w[4] = {w0.x, w0.y, w0.z, w0.w};
#pragma unroll
            for (int i = 0; i < 8; i++)
#pragma unroll
                for (int j = 0; j < 4; j++) acc[i][j] += a[i] * w[j];
        }
        __syncthreads();
    }

    float bs[4];
#pragma unroll
    for (int j = 0; j < 4; j++) bs[j] = bias ? bias[bn + tx * 4 + j] : 0.f;
#pragma unroll
    for (int i = 0; i < 8; i++) {
        long gm = bm + ty * 8 + i;
        float4 o;
        float* po = &o.x;
#pragma unroll
        for (int j = 0; j < 4; j++) {
            float v = acc[i][j] + bs[j];
            if (ACT == 1) v = fmaxf(v, 0.f);
            if (ACT == 2) v = v > 0.f ? v : 0.01f * v;
            po[j] = v;
        }
        long gn = bn + tx * 4;
        *(float4*)&C[gm * ldc + gn] = o;
        if (C2) *(float4*)&C2[gm * ldc2 + gn] = o;
    }
}

// ------- fused per-agent edge kernel -------
#define SEP 12   // padded se row (10 used + 2 zero)
__global__ void edge_kernel(const float* __restrict__ emb,
                            const float* __restrict__ gum,
                            const float* __restrict__ hm1_w,
                            const float* __restrict__ v_w,
                            const float* __restrict__ v_b,
                            float* __restrict__ out)
{
    int a = blockIdx.x;
    int bb = a >> 5, i = a & 31;
    int tid = threadIdx.x;
    int lane = tid & 31, warp = tid >> 5;

    __shared__ float s_emb[NAG * 11];
    __shared__ float s_WE[DD * 7];   // hm1_w[:, 256:263]
    __shared__ float s_W2[2 * DD];
    __shared__ float s_b2[2];
    __shared__ float s_VW[DD * 10];
    __shared__ float s_vb[DD];
    __shared__ float s_base[DD];
    __shared__ float s_qk[10];
    __shared__ __align__(16) float s_se[NAG][SEP];
    __shared__ float s_sc[NAG];
    __shared__ float s_hw[NAG];
    __shared__ float s_cb[NAG];
    __shared__ float s_red[8 * 10];

    for (int e = tid; e < NAG * 11; e += BLK) s_emb[e] = emb[bb * NAG * 11 + e];
    for (int e = tid; e < DD * 7; e += BLK) s_WE[e] = hm1_w[(e / 7) * 263 + 256 + (e % 7)];
    s_W2[tid] = g_W2e[tid];
    s_W2[DD + tid] = g_W2e[DD + tid];
    for (int e = tid; e < DD * 10; e += BLK) s_VW[e] = v_w[e];
    s_vb[tid] = v_b[tid];
    s_base[tid] = g_BASE[(long)a * DD + tid];
    if (tid < 2) s_b2[tid] = g_b2e[tid];

    // qk[f] = sum_d AE[a,d] * QKW[d,f]
    float av = g_AE[(long)a * DD + tid];
#pragma unroll
    for (int f = 0; f < 10; f++) {
        float p = av * g_QKW[tid * 10 + f];
        for (int o = 16; o; o >>= 1) p += __shfl_down_sync(0xffffffffu, p, o);
        if (lane == 0) s_red[warp * 10 + f] = p;
    }
    __syncthreads();
    if (tid < 10) {
        float s = 0.f;
        for (int w = 0; w < 8; w++) s += s_red[w * 10 + tid];
        s_qk[tid] = s;
    }
    __syncthreads();

    // geometry + raw scores (threads 0..31 = edge j)
    if (tid < NAG) {
        int j = tid;
        s_se[j][10] = 0.f; s_se[j][11] = 0.f;
        if (j == i) {
            s_sc[j] = -1e30f; s_hw[j] = 0.f; s_cb[j] = 0.f;
#pragma unroll
            for (int f = 0; f < 10; f++) s_se[j][f] = 0.f;
        } else {
            const float* ei = &s_emb[i * 11];
            const float* ej = &s_emb[j * 11];
            float dx = ej[0] - ei[0], dy = ej[1] - ei[1];
            float r = sqrtf(dx * dx + dy * dy);
            float hx = ei[2], hy = ei[3];
            float hr = sqrtf(hx * hx + hy * hy);
            float inv = 1.f / (r * hr);
            float se[10];
            se[0] = r * (1.f / 12.f);
            se[1] = (dx * hx + dy * hy) * inv;
            se[2] = (dy * hx - dx * hy) * inv;
            se[3] = ej[2]; se[4] = ej[3];
            se[5] = ej[7]; se[6] = ej[8];
            float gx = ej[9] - ei[0], gy = ej[10] - ei[1];
            float gr = sqrtf(gx * gx + gy * gy);
            float ginv = 1.f / (gr * hr);
            se[7] = gr;
            se[8] = (gx * hx + gy * hy) * ginv;
            se[9] = (gy * hx - gx * hy) * ginv;
            float sc = 0.f;
#pragma unroll
            for (int f = 0; f < 10; f++) { s_se[j][f] = se[f]; sc += s_qk[f] * se[f]; }
            s_sc[j] = sc * 0.0625f;
            int jj = j - (j > i);
            out[OFF_UNN + (long)a * NE + jj] = r;
        }
    }
    __syncthreads();

    // hard logits: each warp owns 4 edges, register-blocked over edges
    {
        int jb = warp * 4;
        float e[4][7];
#pragma unroll
        for (int jj = 0; jj < 4; jj++)
#pragma unroll
            for (int f = 0; f < 7; f++) e[jj][f] = s_se[jb + jj][f];
        float acc0[4] = {0.f, 0.f, 0.f, 0.f}, acc1[4] = {0.f, 0.f, 0.f, 0.f};
#pragma unroll
        for (int t = 0; t < 8; t++) {
            int o = lane + t * 32;
            float base = s_base[o];
            const float* we = &s_WE[o * 7];
            float w0 = we[0], w1 = we[1], w2 = we[2], w3 = we[3],
                  w4 = we[4], w5 = we[5], w6 = we[6];
            float W2a = s_W2[o], W2b = s_W2[DD + o];
#pragma unroll
            for (int jj = 0; jj < 4; jj++) {
                float pre = base + w0 * e[jj][0] + w1 * e[jj][1] + w2 * e[jj][2]
                          + w3 * e[jj][3] + w4 * e[jj][4] + w5 * e[jj][5] + w6 * e[jj][6];
                float rr = fmaxf(pre, 0.f);
                acc0[jj] += W2a * rr;
                acc1[jj] += W2b * rr;
            }
        }
#pragma unroll
        for (int jj = 0; jj < 4; jj++) {
            for (int o = 16; o; o >>= 1) {
                acc0[jj] += __shfl_down_sync(0xffffffffu, acc0[jj], o);
                acc1[jj] += __shfl_down_sync(0xffffffffu, acc1[jj], o);
            }
        }
        if (lane == 0) {
#pragma unroll
            for (int jj = 0; jj < 4; jj++) {
                int j = jb + jj;
                if (j == i) continue;
                float l0 = acc0[jj] + s_b2[0], l1 = acc1[jj] + s_b2[1];
                int jx = j - (j > i);
                long gidx = ((long)a * NE + jx) * 2;
                float u0 = gum[gidx], u1 = gum[gidx + 1];
                float g0 = -logf(-logf(u0 + 1e-10f) + 1e-10f);
                float g1 = -logf(-logf(u1 + 1e-10f) + 1e-10f);
                float z0 = (l0 + g0) * 2.f, z1 = (l1 + g1) * 2.f;
                float zm = fmaxf(z0, z1);
                float x0 = expf(z0 - zm), x1 = expf(z1 - zm);
                float p1 = x1 / (x0 + x1);
                s_hw[j] = p1;
                out[OFF_LOG + (long)a * NE + jx] = l1;
                out[OFF_HW + (long)a * NE + jx] = p1;
            }
        }
    }
    __syncthreads();

    // score softmax, combined, entropy (warp 0)
    if (tid < NAG) {
        float sc = s_sc[tid];
        float m = sc;
        for (int o = 16; o; o >>= 1) m = fmaxf(m, __shfl_xor_sync(0xffffffffu, m, o));
        float ev = (tid == i) ? 0.f : expf(sc - m);
        float sum = ev;
        for (int o = 16; o; o >>= 1) sum += __shfl_xor_sync(0xffffffffu, sum, o);
        float sw = ev / sum;
        float cb = sw * s_hw[tid];
        s_cb[tid] = cb;
        float csum = cb;
        for (int o = 16; o; o >>= 1) csum += __shfl_xor_sync(0xffffffffu, csum, o);
        float cwn = cb / (csum + 1e-6f);
        float ent = (tid == i) ? 0.f : (-cwn * logf(cwn + 1e-6f));
        for (int o = 16; o; o >>= 1) ent += __shfl_xor_sync(0xffffffffu, ent, o);
        if (tid == 0) g_ENT[a] = ent;
        if (tid != i) out[OFF_CMB + (long)a * NE + (tid - (tid > i))] = cb;
    }
    __syncthreads();

    // x[a, o] = sum_j combined_j * relu(v_w[o]·se_j + v_b[o])  (float4 se reads)
    {
        int o = tid;
        float vb = s_vb[o];
        float vw[10];
#pragma unroll
        for (int f = 0; f < 10; f++) vw[f] = s_VW[o * 10 + f];
        float acc = 0.f;
#pragma unroll 4
        for (int j = 0; j < NAG; j++) {
            float c = s_cb[j];   // 0 for j==i
            float4 p0 = *(const float4*)&s_se[j][0];
            float4 p1 = *(const float4*)&s_se[j][4];
            float4 p2 = *(const float4*)&s_se[j][8];   // .z/.w are zero pad
            float vv = vb;
            vv += vw[0] * p0.x + vw[1] * p0.y + vw[2] * p0.z + vw[3] * p0.w;
            vv += vw[4] * p1.x + vw[5] * p1.y + vw[6] * p1.z + vw[7] * p1.w;
            vv += vw[8] * p2.x + vw[9] * p2.y;
            acc += c * fmaxf(vv, 0.f);
        }
        g_FIN[(long)a * 512 + 256 + o] = acc;
    }
}

// ------- deterministic entropy reduction -------
__global__ void ent_reduce(const float* __restrict__ ent, float* __restrict__ out)
{
    __shared__ float s[256];
    float v = 0.f;
    for (int k = threadIdx.x; k < NA; k += 256) v += ent[k];
    s[threadIdx.x] = v;
    __syncthreads();
    for (int o = 128; o; o >>= 1) {
        if (threadIdx.x < o) s[threadIdx.x] += s[threadIdx.x + o];
        __syncthreads();
    }
    if (threadIdx.x == 0) out[0] = s[0] * (1.f / 4096.f);
}

extern "C" void kernel_launch(void* const* d_in, const int* in_sizes, int n_in,
                              void* d_out, int out_size)
{
    const float* emb   = (const float*)d_in[0];
    const float* gum   = (const float*)d_in[1];
    const float* emb1w = (const float*)d_in[2];
    const float* emb1b = (const float*)d_in[3];
    const float* emb2w = (const float*)d_in[4];
    const float* emb2b = (const float*)d_in[5];
    const float* hm1w  = (const float*)d_in[6];
    const float* hm1b  = (const float*)d_in[7];
    const float* hm2w  = (const float*)d_in[8];
    const float* hm2b  = (const float*)d_in[9];
    const float* hew   = (const float*)d_in[10];
    const float* heb   = (const float*)d_in[11];
    const float* qw    = (const float*)d_in[12];
    const float* kw    = (const float*)d_in[13];
    const float* vw    = (const float*)d_in[14];
    const float* vb    = (const float*)d_in[15];
    const float* decw  = (const float*)d_in[16];
    const float* decb  = (const float*)d_in[17];
    float* out = (float*)d_out;

    float *pH1, *pAE, *pBASE, *pFIN, *pENT;
    cudaGetSymbolAddress((void**)&pH1, g_H1);
    cudaGetSymbolAddress((void**)&pAE, g_AE);
    cudaGetSymbolAddress((void**)&pBASE, g_BASE);
    cudaGetSymbolAddress((void**)&pFIN, g_FIN);
    cudaGetSymbolAddress((void**)&pENT, g_ENT);

    foldA_kernel<<<8, 256>>>(hew, hm2w, hm2b, qw, kw);
    foldB_kernel<<<1, 256>>>(heb);

    // H1 = leaky(emb[:,4:9] @ emb1_w^T + b)
    h1_kernel<<<NA / 2, 256>>>(emb, emb1w, emb1b, pH1);
    // AE = leaky(H1 @ emb2_w^T + b); mirror into FIN[:, 0:256]
    gemm_t2<2><<<dim3(256 / 64, NA / 64), 128>>>(pH1, 128, emb2w, 128, emb2b,
                                                 pAE, 256, pFIN, 512, 128);
    // BASE = AE @ hm1_w[:, :256]^T + hm1_b
    gemm_t2<0><<<dim3(256 / 64, NA / 64), 128>>>(pAE, 256, hm1w, 263, hm1b,
                                                 pBASE, 256, nullptr, 0, 256);
    // fused per-agent edge pipeline; writes FIN[:, 256:512] and 4 outputs
    edge_kernel<<<NA, 256>>>(emb, gum, hm1w, vw, vb, out);
    // output = FIN @ dec_w^T + dec_b
    gemm_t2<0><<<dim3(512 / 64, NA / 64), 128>>>(pFIN, 512, decw, 512, decb,
                                                 out, 512, nullptr, 0, 512);
    // mean entropy
    ent_reduce<<<1, 256>>>(pENT, out + OFF_ENT);
}